// round 3
// baseline (speedup 1.0000x reference)
#include <cuda_runtime.h>

#define NN     256
#define NS     512
#define MAXSP  32
#define NSTEPS 32
#define VRESET 1.0f
#define JPT    8          // neurons per thread (NN / 32)
#define WPB    4          // warps (samples) per block

__device__ __forceinline__ float sigmoidf_(float x) {
    return 1.0f / (1.0f + expf(-x));
}

__global__ void __launch_bounds__(32 * WPB) snn_kernel(
    const float* __restrict__ input_current,  // [NN]
    const float* __restrict__ w,              // [NN, NN]
    const float* __restrict__ mu,             // [2]
    const float* __restrict__ v0,             // [NN]
    const float* __restrict__ i0,             // [NN]
    const float* __restrict__ s0,             // [NS, NN]
    const float* __restrict__ reset_s,        // [MAXSP, NS, NN]
    const int*   __restrict__ t1_raw,
    float* __restrict__ out_times,            // [NS, MAXSP]
    float* __restrict__ out_vals,             // [NS, MAXSP, NN, 3]
    float* __restrict__ out_marks)            // [NS, MAXSP, NN]
{
    const int wid  = threadIdx.x >> 5;
    const int s    = blockIdx.x * WPB + wid;   // one sample per warp
    const int lane = threadIdx.x & 31;
    const unsigned FULL = 0xffffffffu;

    // t1 dtype sniffing: small positive int -> integer payload; else float bits
    float t1f;
    {
        int iv = t1_raw[0];
        if (iv > 0 && iv < 1000000) t1f = (float)iv;
        else                        t1f = __int_as_float(iv);
    }

    const float mu1 = mu[0];
    const float mu2 = mu[1];

    float ic[JPT], yv[JPT], yi[JPT], ys[JPT];
    #pragma unroll
    for (int j = 0; j < JPT; ++j) {
        const int n = 32 * j + lane;
        ic[j] = input_current[n];
        yv[j] = v0[n];
        yi[j] = i0[n];
        ys[j] = s0[s * NN + n];
    }
    float t0s = 0.0f;

    for (int k = 0; k < MAXSP; ++k) {
        const float dt = (t1f - t0s) / (float)NSTEPS;
        const float h  = dt;
        const float hh = 0.5f * h;
        const float h6 = h / 6.0f;

        float tev = t1f;
        bool  trig = false;
        int   emask = 0;   // bit j set <=> neuron 32j+lane crossed at event

        if (dt != 0.0f) {
            float t = t0s;
            for (int step = 0; step < NSTEPS; ++step) {
                float nv[JPT], ni[JPT], ns[JPT];
                bool anyl = false;
                #pragma unroll
                for (int j = 0; j < JPT; ++j) {
                    // ---- RK4 (mirror reference op order) ----
                    float k1v = mu1 * ((yi[j] + ic[j]) - yv[j]);
                    float k1i = -mu2 * yi[j];
                    float k1s = sigmoidf_(yv[j]);
                    float v2 = yv[j] + hh * k1v, i2 = yi[j] + hh * k1i;
                    float k2v = mu1 * ((i2 + ic[j]) - v2);
                    float k2i = -mu2 * i2;
                    float k2s = sigmoidf_(v2);
                    float v3 = yv[j] + hh * k2v, i3 = yi[j] + hh * k2i;
                    float k3v = mu1 * ((i3 + ic[j]) - v3);
                    float k3i = -mu2 * i3;
                    float k3s = sigmoidf_(v3);
                    float v4 = yv[j] + h * k3v, i4 = yi[j] + h * k3i;
                    float k4v = mu1 * ((i4 + ic[j]) - v4);
                    float k4i = -mu2 * i4;
                    float k4s = sigmoidf_(v4);
                    nv[j] = yv[j] + h6 * (k1v + 2.0f * k2v + 2.0f * k3v + k4v);
                    ni[j] = yi[j] + h6 * (k1i + 2.0f * k2i + 2.0f * k3i + k4i);
                    ns[j] = ys[j] + h6 * (k1s + 2.0f * k2s + 2.0f * k3s + k4s);
                    anyl |= (ns[j] > 0.0f);
                }

                if (__any_sync(FULL, anyl)) {
                    // ---- full argmax(s_new) with first-index tie-break ----
                    float bv = ns[0]; int bi = lane;
                    #pragma unroll
                    for (int j = 1; j < JPT; ++j) {
                        if (ns[j] > bv) { bv = ns[j]; bi = 32 * j + lane; }
                    }
                    #pragma unroll
                    for (int o = 16; o > 0; o >>= 1) {
                        float ov = __shfl_xor_sync(FULL, bv, o);
                        int   oi = __shfl_xor_sync(FULL, bi, o);
                        if (ov > bv || (ov == bv && oi < bi)) { bv = ov; bi = oi; }
                    }
                    const int mi = bi;   // argmax neuron index (uniform)

                    // fetch s_prev/s_new of argmax neuron
                    float spv = 0.0f, snv = 0.0f;
                    #pragma unroll
                    for (int j = 0; j < JPT; ++j) {
                        if (32 * j + lane == mi) { spv = ys[j]; snv = ns[j]; }
                    }
                    const float sp = __shfl_sync(FULL, spv, mi & 31);
                    const float sn = __shfl_sync(FULL, snv, mi & 31);

                    float frac = sp / (sp - sn + 1e-12f);
                    frac = fminf(fmaxf(frac, 0.0f), 1.0f);
                    tev = t + frac * dt;
                    #pragma unroll
                    for (int j = 0; j < JPT; ++j) {
                        yv[j] = yv[j] + frac * (nv[j] - yv[j]);
                        yi[j] = yi[j] + frac * (ni[j] - yi[j]);
                        ys[j] = ys[j] + frac * (ns[j] - ys[j]);
                        if (ns[j] > 0.0f) emask |= (1 << j);
                    }
                    trig = true;
                    break;
                }
                #pragma unroll
                for (int j = 0; j < JPT; ++j) { yv[j] = nv[j]; yi[j] = ni[j]; ys[j] = ns[j]; }
                t += dt;
            }
        }

        // ---- outputs (event state = current y) ----
        if (lane == 0) out_times[s * MAXSP + k] = tev;
        const long row = (long)(s * MAXSP + k);
        #pragma unroll
        for (int j = 0; j < JPT; ++j) {
            const int n = 32 * j + lane;
            const long base = (row * NN + n) * 3;
            out_vals[base + 0] = yv[j];
            out_vals[base + 1] = yi[j];
            out_vals[base + 2] = ys[j];
            out_marks[row * NN + n] = (emask >> j) & 1 ? 1.0f : 0.0f;
        }

        // ---- next-round state ----
        if (trig) {
            // eidx = first neuron index with emask set (global across warp)
            int eidx = 0;
            #pragma unroll
            for (int j = 0; j < JPT; ++j) {
                unsigned b = __ballot_sync(FULL, (emask >> j) & 1);
                if (b) { eidx = 32 * j + __ffs(b) - 1; break; }
            }
            #pragma unroll
            for (int j = 0; j < JPT; ++j) {
                const bool em = (emask >> j) & 1;
                yv[j] = yv[j] - (em ? VRESET : 0.0f);
                yi[j] = yi[j] + w[eidx * NN + 32 * j + lane];
                const float rs = reset_s[((long)k * NS + s) * NN + 32 * j + lane];
                ys[j] = fminf(em ? rs : ys[j], 0.0f);
            }
        } else {
            #pragma unroll
            for (int j = 0; j < JPT; ++j) ys[j] = fminf(ys[j], 0.0f);
        }
        t0s = tev;
    }
}

extern "C" void kernel_launch(void* const* d_in, const int* in_sizes, int n_in,
                              void* d_out, int out_size) {
    const float* input_current = (const float*)d_in[0];
    const float* w             = (const float*)d_in[1];
    const float* mu            = (const float*)d_in[2];
    const float* v0            = (const float*)d_in[3];
    const float* i0            = (const float*)d_in[4];
    const float* s0            = (const float*)d_in[5];
    const float* reset_s       = (const float*)d_in[6];
    const int*   t1            = (const int*)  d_in[7];

    float* out = (float*)d_out;
    float* out_times = out;                                      // 512*32
    float* out_vals  = out + (long)NS * MAXSP;                   // 512*32*256*3
    float* out_marks = out + (long)NS * MAXSP
                           + (long)NS * MAXSP * NN * 3;          // 512*32*256

    snn_kernel<<<NS / WPB, 32 * WPB>>>(input_current, w, mu, v0, i0, s0, reset_s, t1,
                                       out_times, out_vals, out_marks);
}

// round 4
// speedup vs baseline: 2.6794x; 2.6794x over previous
#include <cuda_runtime.h>

#define NN     256
#define NS     512
#define MAXSP  32
#define NSTEPS 32
#define VRESET 1.0f
#define JPT    2            // neurons per thread
#define NT     128          // threads per block (NN / JPT)
#define NWARP  (NT / 32)

__device__ __forceinline__ float sigmoidf_(float x) {
    float e = __expf(-x);
    return __fdividef(1.0f, 1.0f + e);
}

__global__ void __launch_bounds__(NT) snn_kernel(
    const float* __restrict__ input_current,  // [NN]
    const float* __restrict__ w,              // [NN, NN]
    const float* __restrict__ mu,             // [2]
    const float* __restrict__ v0,             // [NN]
    const float* __restrict__ i0,             // [NN]
    const float* __restrict__ s0,             // [NS, NN]
    const float* __restrict__ reset_s,        // [MAXSP, NS, NN]
    const int*   __restrict__ t1_raw,
    float* __restrict__ out_times,            // [NS, MAXSP]
    float* __restrict__ out_vals,             // [NS, MAXSP, NN, 3]
    float* __restrict__ out_marks)            // [NS, MAXSP, NN]
{
    const int s    = blockIdx.x;
    const int tid  = threadIdx.x;
    const int wid  = tid >> 5;
    const int lane = tid & 31;
    const unsigned FULL = 0xffffffffu;

    __shared__ float    red_v[NWARP];
    __shared__ int      red_i[NWARP];
    __shared__ float    sp_sh, sn_sh;
    __shared__ unsigned ball[2 * NWARP];

    // t1 dtype sniffing: small positive int -> integer payload; else float bits
    float t1f;
    {
        int iv = t1_raw[0];
        if (iv > 0 && iv < 1000000) t1f = (float)iv;
        else                        t1f = __int_as_float(iv);
    }

    const float mu1 = mu[0];
    const float mu2 = mu[1];

    // neuron indices: n_j = tid + j*NT (coalesced)
    float ic[JPT], yv[JPT], yi[JPT], ys[JPT];
    #pragma unroll
    for (int j = 0; j < JPT; ++j) {
        const int n = tid + j * NT;
        ic[j] = input_current[n];
        yv[j] = v0[n];
        yi[j] = i0[n];
        ys[j] = s0[s * NN + n];
    }
    float t0s = 0.0f;

    for (int k = 0; k < MAXSP; ++k) {
        const float dt = (t1f - t0s) / (float)NSTEPS;
        const float h  = dt;
        const float hh = 0.5f * h;
        const float h6 = h / 6.0f;

        float tev  = t1f;
        bool  trig = false;
        int   emask = 0;       // bit j: neuron tid + j*NT crossed at event

        if (dt != 0.0f) {
            float t = t0s;
            for (int step = 0; step < NSTEPS; ++step) {
                float nv[JPT], ni[JPT], ns[JPT];
                int anyl = 0;
                #pragma unroll
                for (int j = 0; j < JPT; ++j) {
                    // ---- RK4 (reference op order, fast sigmoid) ----
                    float k1v = mu1 * ((yi[j] + ic[j]) - yv[j]);
                    float k1i = -mu2 * yi[j];
                    float k1s = sigmoidf_(yv[j]);
                    float v2 = yv[j] + hh * k1v, i2 = yi[j] + hh * k1i;
                    float k2v = mu1 * ((i2 + ic[j]) - v2);
                    float k2i = -mu2 * i2;
                    float k2s = sigmoidf_(v2);
                    float v3 = yv[j] + hh * k2v, i3 = yi[j] + hh * k2i;
                    float k3v = mu1 * ((i3 + ic[j]) - v3);
                    float k3i = -mu2 * i3;
                    float k3s = sigmoidf_(v3);
                    float v4 = yv[j] + h * k3v, i4 = yi[j] + h * k3i;
                    float k4v = mu1 * ((i4 + ic[j]) - v4);
                    float k4i = -mu2 * i4;
                    float k4s = sigmoidf_(v4);
                    nv[j] = yv[j] + h6 * (k1v + 2.0f * k2v + 2.0f * k3v + k4v);
                    ni[j] = yi[j] + h6 * (k1i + 2.0f * k2i + 2.0f * k3i + k4i);
                    ns[j] = ys[j] + h6 * (k1s + 2.0f * k2s + 2.0f * k3s + k4s);
                    anyl |= (ns[j] > 0.0f) ? 1 : 0;
                }

                // single hardware BAR.RED per step — trigger fast path
                if (__syncthreads_or(anyl)) {
                    // ---- full argmax(s_new), first-index tie-break ----
                    float bv = ns[0]; int bi = tid;
                    #pragma unroll
                    for (int j = 1; j < JPT; ++j) {
                        const int nj = tid + j * NT;
                        if (ns[j] > bv || (ns[j] == bv && nj < bi)) { bv = ns[j]; bi = nj; }
                    }
                    #pragma unroll
                    for (int o = 16; o > 0; o >>= 1) {
                        float ov = __shfl_xor_sync(FULL, bv, o);
                        int   oi = __shfl_xor_sync(FULL, bi, o);
                        if (ov > bv || (ov == bv && oi < bi)) { bv = ov; bi = oi; }
                    }
                    if (lane == 0) { red_v[wid] = bv; red_i[wid] = bi; }
                    __syncthreads();
                    float mv = red_v[0]; int mi = red_i[0];
                    #pragma unroll
                    for (int ww = 1; ww < NWARP; ++ww) {
                        float ov = red_v[ww]; int oi = red_i[ww];
                        if (ov > mv || (ov == mv && oi < mi)) { mv = ov; mi = oi; }
                    }
                    // owner publishes s_prev / s_new of argmax neuron
                    #pragma unroll
                    for (int j = 0; j < JPT; ++j) {
                        if (tid + j * NT == mi) { sp_sh = ys[j]; sn_sh = ns[j]; }
                    }
                    __syncthreads();
                    const float sp = sp_sh, sn = sn_sh;
                    float frac = sp / (sp - sn + 1e-12f);
                    frac = fminf(fmaxf(frac, 0.0f), 1.0f);
                    tev = t + frac * dt;
                    #pragma unroll
                    for (int j = 0; j < JPT; ++j) {
                        yv[j] = yv[j] + frac * (nv[j] - yv[j]);
                        yi[j] = yi[j] + frac * (ni[j] - yi[j]);
                        ys[j] = ys[j] + frac * (ns[j] - ys[j]);
                        if (ns[j] > 0.0f) emask |= (1 << j);
                    }
                    trig = true;
                    break;
                }
                #pragma unroll
                for (int j = 0; j < JPT; ++j) { yv[j] = nv[j]; yi[j] = ni[j]; ys[j] = ns[j]; }
                t += dt;
            }
        }

        // ---- outputs (event state = current y) ----
        if (tid == 0) out_times[s * MAXSP + k] = tev;
        const long row = (long)(s * MAXSP + k);
        #pragma unroll
        for (int j = 0; j < JPT; ++j) {
            const int n = tid + j * NT;
            const long base = (row * NN + n) * 3;
            out_vals[base + 0] = yv[j];
            out_vals[base + 1] = yi[j];
            out_vals[base + 2] = ys[j];
            out_marks[row * NN + n] = (emask >> j) & 1 ? 1.0f : 0.0f;
        }

        // ---- next-round state ----
        if (trig) {
            // eidx = first neuron index (0..255) with event mark
            #pragma unroll
            for (int j = 0; j < JPT; ++j) {
                unsigned b = __ballot_sync(FULL, (emask >> j) & 1);
                if (lane == 0) ball[j * NWARP + wid] = b;
            }
            __syncthreads();
            int eidx = 0;
            #pragma unroll
            for (int q = 0; q < 2 * NWARP; ++q) {   // q = j*NWARP + w -> neurons j*NT + 32w ..
                unsigned bb = ball[q];
                if (bb) { eidx = (q / NWARP) * NT + (q % NWARP) * 32 + __ffs(bb) - 1; break; }
            }
            #pragma unroll
            for (int j = 0; j < JPT; ++j) {
                const int n = tid + j * NT;
                const bool em = (emask >> j) & 1;
                yv[j] = yv[j] - (em ? VRESET : 0.0f);
                yi[j] = yi[j] + w[eidx * NN + n];
                const float rs = reset_s[((long)k * NS + s) * NN + n];
                ys[j] = fminf(em ? rs : ys[j], 0.0f);
            }
        } else {
            #pragma unroll
            for (int j = 0; j < JPT; ++j) ys[j] = fminf(ys[j], 0.0f);
        }
        t0s = tev;
        __syncthreads();   // smem reuse guard across rounds (uniform)
    }
}

extern "C" void kernel_launch(void* const* d_in, const int* in_sizes, int n_in,
                              void* d_out, int out_size) {
    const float* input_current = (const float*)d_in[0];
    const float* w             = (const float*)d_in[1];
    const float* mu            = (const float*)d_in[2];
    const float* v0            = (const float*)d_in[3];
    const float* i0            = (const float*)d_in[4];
    const float* s0            = (const float*)d_in[5];
    const float* reset_s       = (const float*)d_in[6];
    const int*   t1            = (const int*)  d_in[7];

    float* out = (float*)d_out;
    float* out_times = out;                                      // 512*32
    float* out_vals  = out + (long)NS * MAXSP;                   // 512*32*256*3
    float* out_marks = out + (long)NS * MAXSP
                           + (long)NS * MAXSP * NN * 3;          // 512*32*256

    snn_kernel<<<NS, NT>>>(input_current, w, mu, v0, i0, s0, reset_s, t1,
                           out_times, out_vals, out_marks);
}